// round 10
// baseline (speedup 1.0000x reference)
#include <cuda_runtime.h>
#include <cuda_fp16.h>
#include <cstdint>

#define LSEQ 8192
#define DIM  2048
#define NCHUNK 64
#define CHUNK 128

// ---------------- scratch (__device__ globals; no allocation) ---------------
__device__ __half g_xmh[(size_t)LSEQ * DIM];   // x_mix, fp16
__device__ __half g_wh[(size_t)DIM * DIM];     // W, fp16
__device__ float g_carry[NCHUNK * DIM];
__device__ float g_mprev[NCHUNK * DIM];

__device__ __forceinline__ float sigmoidf_(float p) { return 1.0f / (1.0f + expf(-p)); }

// ---------------------------------------------------------------------------
// Pass A: per-chunk carry only (zero-seeded local scan)
// ---------------------------------------------------------------------------
__global__ void carryscan_kernel(const float* __restrict__ x,
                                 const float* __restrict__ fparam) {
    int d = blockIdx.x * blockDim.x + threadIdx.x;
    int c = blockIdx.y;
    float f = sigmoidf_(fparam[d]);
    float omf = 1.0f - f;
    const float* xp = x + (size_t)c * CHUNK * DIM + d;
    float y = 0.0f;
#pragma unroll 16
    for (int i = 0; i < CHUNK; i++)
        y = fmaf(f, y, omf * xp[(size_t)i * DIM]);
    g_carry[c * DIM + d] = y;
}

// ---------------------------------------------------------------------------
// Pass B: serial combine of chunk carries.
// ---------------------------------------------------------------------------
__global__ void carry_kernel(const float* __restrict__ fparam,
                             const float* __restrict__ xml) {
    int d = blockIdx.x * blockDim.x + threadIdx.x;
    float f = sigmoidf_(fparam[d]);
    float fC = f;
#pragma unroll
    for (int i = 0; i < 7; i++) fC *= fC;   // f^128
    float m = xml[d];
#pragma unroll 4
    for (int c = 0; c < NCHUNK; c++) {
        g_mprev[c * DIM + d] = m;
        m = fmaf(fC, m, g_carry[c * DIM + d]);
    }
}

// ---------------------------------------------------------------------------
// Pass C (fused): seeded rescan -> fp16 x_mix  AND  W -> fp16 conversion.
// blockIdx.y < NCHUNK: scan chunk.  blockIdx.y >= NCHUNK: W chunk (2 float4s).
// ---------------------------------------------------------------------------
#define WBY 256            // extra blockIdx.y rows for W conversion
__global__ void scanw_kernel(const float* __restrict__ x,
                             const float* __restrict__ fparam,
                             const float* __restrict__ W) {
    if (blockIdx.y < NCHUNK) {
        int d = blockIdx.x * blockDim.x + threadIdx.x;
        int c = blockIdx.y;
        float f = sigmoidf_(fparam[d]);
        float omf = 1.0f - f;
        const float* xp = x + (size_t)c * CHUNK * DIM + d;
        __half* yp = g_xmh + (size_t)c * CHUNK * DIM + d;
        float y = g_mprev[c * DIM + d];
#pragma unroll 16
        for (int i = 0; i < CHUNK; i++) {
            y = fmaf(f, y, omf * xp[(size_t)i * DIM]);
            yp[(size_t)i * DIM] = __float2half_rn(y);
        }
    } else {
        // 512K threads, 2 float4 each -> 1M float4 = DIM*DIM floats
        int q = ((blockIdx.y - NCHUNK) * gridDim.x + blockIdx.x) * blockDim.x + threadIdx.x;
        const int HALF_ELEMS = (DIM * DIM / 4) / 2;   // 524288
        float4 v0 = ((const float4*)W)[q];
        float4 v1 = ((const float4*)W)[q + HALF_ELEMS];
        ((__half2*)g_wh)[q * 2]     = __floats2half2_rn(v0.x, v0.y);
        ((__half2*)g_wh)[q * 2 + 1] = __floats2half2_rn(v0.z, v0.w);
        ((__half2*)g_wh)[(q + HALF_ELEMS) * 2]     = __floats2half2_rn(v1.x, v1.y);
        ((__half2*)g_wh)[(q + HALF_ELEMS) * 2 + 1] = __floats2half2_rn(v1.z, v1.w);
    }
}

// ---------------------------------------------------------------------------
// fp16 mma.sync GEMM:  out[m,n] = sum_k A[m,k] * W[n,k]  (fp32 accum)
// Block 256x128x64, 256 threads = 8 warps (4m x 2n), warp tile 64x64.
// mma.m16n8k16, ldmatrix.x4, XOR-swizzled 128B rows, 4-stage cp.async ring
// (distance 2), fragment double-buffering. cp.async issues are placed AFTER
// the fragment priming so LDSMs aren't queued behind the LSU burst.
// ---------------------------------------------------------------------------
#define BM 256
#define BN 128
#define BK 64                                  // halfs; 128 bytes per row
#define KTILES (DIM / BK)                      // 32
#define A_BYTES (BM * 128)                     // 32768
#define B_BYTES (BN * 128)                     // 16384
#define STAGE_BYTES (A_BYTES + B_BYTES)        // 49152
#define NSTAGE 4
#define SM_BYTES (NSTAGE * STAGE_BYTES)        // 196608

#define MMA_F16(c, a, b0, b1)                                                 \
    asm volatile(                                                             \
        "mma.sync.aligned.m16n8k16.row.col.f32.f16.f16.f32 "                  \
        "{%0,%1,%2,%3},{%4,%5,%6,%7},{%8,%9},{%0,%1,%2,%3};\n"                \
        : "+f"((c)[0]), "+f"((c)[1]), "+f"((c)[2]), "+f"((c)[3])              \
        : "r"((a)[0]), "r"((a)[1]), "r"((a)[2]), "r"((a)[3]),                 \
          "r"(b0), "r"(b1))

__device__ __forceinline__ uint32_t smem_u32(const void* p) {
    uint32_t a;
    asm("{ .reg .u64 t; cvta.to.shared.u64 t, %1; cvt.u32.u64 %0, t; }" : "=r"(a) : "l"(p));
    return a;
}
__device__ __forceinline__ void cp16(uint32_t dst, const void* src) {
    asm volatile("cp.async.cg.shared.global [%0], [%1], 16;" :: "r"(dst), "l"(src));
}
__device__ __forceinline__ void cp_commit() {
    asm volatile("cp.async.commit_group;");
}
template <int N>
__device__ __forceinline__ void cp_wait() {
    asm volatile("cp.async.wait_group %0;" :: "n"(N));
}
__device__ __forceinline__ void ldsm4(unsigned* r, uint32_t addr) {
    asm volatile("ldmatrix.sync.aligned.m8n8.x4.shared.b16 {%0,%1,%2,%3}, [%4];"
                 : "=r"(r[0]), "=r"(r[1]), "=r"(r[2]), "=r"(r[3]) : "r"(addr));
}

__global__ __launch_bounds__(256, 1) void gemm_kernel(float* __restrict__ out) {
    extern __shared__ char smc[];
    uint32_t sb = smem_u32(smc);

    int tid = threadIdx.x;
    int bm = blockIdx.y * BM, bn = blockIdx.x * BN;
    int warp = tid >> 5, lane = tid & 31;
    int wm = (warp & 3) * 64, wn = (warp >> 2) * 64;
    int grp = lane >> 2, tig = lane & 3;

    // cp.async thread mapping: 16B chunks, swizzle chunk ^= row&7
    int lrow = tid >> 3;            // 0..31
    int lch = tid & 7;              // chunk 0..7
    uint32_t stoffA = lrow * 128 + ((lch ^ (lrow & 7)) << 4);
    uint32_t stoffB = A_BYTES + stoffA;

    const __half* Ag = g_xmh + (size_t)(bm + lrow) * DIM + lch * 8;
    const __half* Bg = g_wh + (size_t)(bn + lrow) * DIM + lch * 8;

    // ldmatrix per-lane address components
    uint32_t aBase[4]; int aR7[4];
    int aCC = lane >> 4;            // kc parity offset
    {
        int r = (lane & 7) + ((lane >> 3) & 1) * 8;
#pragma unroll
        for (int mt = 0; mt < 4; mt++) {
            int row = wm + mt * 16 + r;
            aBase[mt] = row * 128;
            aR7[mt] = row & 7;
        }
    }
    uint32_t bBase[4]; int bR7[4];
    int bCC = (lane >> 3) & 1;
    {
        int r = (lane & 7) + ((lane >> 4) & 1) * 8;
#pragma unroll
        for (int p = 0; p < 4; p++) {
            int row = wn + p * 16 + r;
            bBase[p] = A_BYTES + row * 128;
            bR7[p] = row & 7;
        }
    }

    float acc[4][8][4] = {};

    auto issue = [&](int t) {
        uint32_t base = sb + (t & (NSTAGE - 1)) * STAGE_BYTES;
        const __half* Ak = Ag + t * BK;
        const __half* Bk = Bg + t * BK;
#pragma unroll
        for (int o = 0; o < 8; o++)
            cp16(base + stoffA + o * (32 * 128), Ak + (size_t)(o * 32) * DIM);
#pragma unroll
        for (int o = 0; o < 4; o++)
            cp16(base + stoffB + o * (32 * 128), Bk + (size_t)(o * 32) * DIM);
        cp_commit();
    };

    issue(0);
    issue(1);

    for (int j = 0; j < KTILES; j++) {
        // outstanding groups here: {j, j+1} (or {j} on the last iter)
        if (j + 1 < KTILES) { cp_wait<1>(); }
        else { cp_wait<0>(); }
        __syncthreads();   // stage-j visibility to all warps; also guarantees
                           // slot (j+2)%4 (last read at iter j-2) is drained

        uint32_t st = sb + (j & (NSTAGE - 1)) * STAGE_BYTES;

        unsigned a[2][4][4], b[2][4][4];
        // prime ks=0 fragments first (they gate the first MMA)
#pragma unroll
        for (int mt = 0; mt < 4; mt++)
            ldsm4(a[0][mt], st + aBase[mt] + ((aCC ^ aR7[mt]) << 4));
#pragma unroll
        for (int p = 0; p < 4; p++)
            ldsm4(b[0][p], st + bBase[p] + ((bCC ^ bR7[p]) << 4));

        // then enqueue the next prefetch behind the LDSMs
        if (j + 2 < KTILES) issue(j + 2);

#pragma unroll
        for (int ks = 0; ks < 4; ks++) {
            int cur = ks & 1, nxt = cur ^ 1;
            if (ks < 3) {
                int kc = 2 * (ks + 1);
#pragma unroll
                for (int mt = 0; mt < 4; mt++)
                    ldsm4(a[nxt][mt], st + aBase[mt] + (((kc + aCC) ^ aR7[mt]) << 4));
#pragma unroll
                for (int p = 0; p < 4; p++)
                    ldsm4(b[nxt][p], st + bBase[p] + (((kc + bCC) ^ bR7[p]) << 4));
            }
#pragma unroll
            for (int mt = 0; mt < 4; mt++)
#pragma unroll
                for (int p = 0; p < 4; p++) {
                    MMA_F16(acc[mt][2 * p], a[cur][mt], b[cur][p][0], b[cur][p][1]);
                    MMA_F16(acc[mt][2 * p + 1], a[cur][mt], b[cur][p][2], b[cur][p][3]);
                }
        }
    }

    // ---- epilogue: float2 stores ----
#pragma unroll
    for (int mt = 0; mt < 4; mt++) {
#pragma unroll
        for (int nt = 0; nt < 8; nt++) {
            int row = bm + wm + mt * 16 + grp;
            int col = bn + wn + nt * 8 + tig * 2;
            float2 v0 = make_float2(acc[mt][nt][0], acc[mt][nt][1]);
            float2 v1 = make_float2(acc[mt][nt][2], acc[mt][nt][3]);
            *(float2*)(out + (size_t)row * DIM + col) = v0;
            *(float2*)(out + (size_t)(row + 8) * DIM + col) = v1;
        }
    }
}

// ---------------------------------------------------------------------------
extern "C" void kernel_launch(void* const* d_in, const int* in_sizes, int n_in,
                              void* d_out, int out_size) {
    const float* x      = (const float*)d_in[0];
    const float* xml    = (const float*)d_in[1];
    const float* fparam = (const float*)d_in[2];
    const float* W      = (const float*)d_in[3];
    float* out = (float*)d_out;

    carryscan_kernel<<<dim3(DIM / 256, NCHUNK), 256>>>(x, fparam);
    carry_kernel<<<DIM / 256, 256>>>(fparam, xml);
    scanw_kernel<<<dim3(DIM / 256, NCHUNK + WBY), 256>>>(x, fparam, W);

    static bool attr_set = false;
    if (!attr_set) {
        cudaFuncSetAttribute(gemm_kernel, cudaFuncAttributeMaxDynamicSharedMemorySize, SM_BYTES);
        attr_set = true;
    }
    gemm_kernel<<<dim3(DIM / BN, LSEQ / BM), 256, SM_BYTES>>>(out);
}

// round 11
// speedup vs baseline: 1.1391x; 1.1391x over previous
#include <cuda_runtime.h>
#include <cuda_fp16.h>
#include <cstdint>

#define LSEQ 8192
#define DIM  2048
#define NCHUNK 64
#define CHUNK 128

// ---------------- scratch (__device__ globals; no allocation) ---------------
__device__ __half g_xmh[(size_t)LSEQ * DIM];   // x_mix, fp16
__device__ __half g_wh[(size_t)DIM * DIM];     // W, fp16
__device__ float g_carry[NCHUNK * DIM];
__device__ float g_mprev[NCHUNK * DIM];

__device__ __forceinline__ float sigmoidf_(float p) { return 1.0f / (1.0f + expf(-p)); }

// ---------------------------------------------------------------------------
// Pass A: per-chunk carry only (zero-seeded local scan)
// ---------------------------------------------------------------------------
__global__ void carryscan_kernel(const float* __restrict__ x,
                                 const float* __restrict__ fparam) {
    int d = blockIdx.x * blockDim.x + threadIdx.x;
    int c = blockIdx.y;
    float f = sigmoidf_(fparam[d]);
    float omf = 1.0f - f;
    const float* xp = x + (size_t)c * CHUNK * DIM + d;
    float y = 0.0f;
#pragma unroll 16
    for (int i = 0; i < CHUNK; i++)
        y = fmaf(f, y, omf * xp[(size_t)i * DIM]);
    g_carry[c * DIM + d] = y;
}

// ---------------------------------------------------------------------------
// Pass B: serial combine of chunk carries.
// ---------------------------------------------------------------------------
__global__ void carry_kernel(const float* __restrict__ fparam,
                             const float* __restrict__ xml) {
    int d = blockIdx.x * blockDim.x + threadIdx.x;
    float f = sigmoidf_(fparam[d]);
    float fC = f;
#pragma unroll
    for (int i = 0; i < 7; i++) fC *= fC;   // f^128
    float m = xml[d];
#pragma unroll 4
    for (int c = 0; c < NCHUNK; c++) {
        g_mprev[c * DIM + d] = m;
        m = fmaf(fC, m, g_carry[c * DIM + d]);
    }
}

// ---------------------------------------------------------------------------
// Pass C: seeded rescan, writes fp16 x_mix.
// ---------------------------------------------------------------------------
__global__ void scan_write_kernel(const float* __restrict__ x,
                                  const float* __restrict__ fparam) {
    int d = blockIdx.x * blockDim.x + threadIdx.x;
    int c = blockIdx.y;
    float f = sigmoidf_(fparam[d]);
    float omf = 1.0f - f;
    const float* xp = x + (size_t)c * CHUNK * DIM + d;
    __half* yp = g_xmh + (size_t)c * CHUNK * DIM + d;
    float y = g_mprev[c * DIM + d];
#pragma unroll 16
    for (int i = 0; i < CHUNK; i++) {
        y = fmaf(f, y, omf * xp[(size_t)i * DIM]);
        yp[(size_t)i * DIM] = __float2half_rn(y);
    }
}

// W -> fp16 copy
__global__ void wconv_kernel(const float* __restrict__ W) {
    int i = blockIdx.x * blockDim.x + threadIdx.x;
    float4 v = ((const float4*)W)[i];
    ((__half2*)g_wh)[i * 2]     = __floats2half2_rn(v.x, v.y);
    ((__half2*)g_wh)[i * 2 + 1] = __floats2half2_rn(v.z, v.w);
}

// ---------------------------------------------------------------------------
// fp16 mma.sync GEMM:  out[m,n] = sum_k A[m,k] * W[n,k]  (fp32 accum)
// Block tile 128x128x64, 128 threads = 4 warps (2m x 2n), warp tile 64x64.
// 2 CTAs co-resident per SM (cross-CTA latency hiding at barriers),
// 3-stage cp.async ring (prefetch distance 2), ldmatrix.x4 fragments,
// XOR-swizzled 128B rows, register double-buffered fragments.
// ---------------------------------------------------------------------------
#define BM 128
#define BN 128
#define BK 64                                  // halfs; 128 bytes per row
#define KTILES (DIM / BK)                      // 32
#define A_BYTES (BM * 128)                     // 16384
#define B_BYTES (BN * 128)                     // 16384
#define STAGE_BYTES (A_BYTES + B_BYTES)        // 32768
#define NSTAGE 3
#define SM_BYTES (NSTAGE * STAGE_BYTES)        // 98304

#define MMA_F16(c, a, b0, b1)                                                 \
    asm volatile(                                                             \
        "mma.sync.aligned.m16n8k16.row.col.f32.f16.f16.f32 "                  \
        "{%0,%1,%2,%3},{%4,%5,%6,%7},{%8,%9},{%0,%1,%2,%3};\n"                \
        : "+f"((c)[0]), "+f"((c)[1]), "+f"((c)[2]), "+f"((c)[3])              \
        : "r"((a)[0]), "r"((a)[1]), "r"((a)[2]), "r"((a)[3]),                 \
          "r"(b0), "r"(b1))

__device__ __forceinline__ uint32_t smem_u32(const void* p) {
    uint32_t a;
    asm("{ .reg .u64 t; cvta.to.shared.u64 t, %1; cvt.u32.u64 %0, t; }" : "=r"(a) : "l"(p));
    return a;
}
__device__ __forceinline__ void cp16(uint32_t dst, const void* src) {
    asm volatile("cp.async.cg.shared.global [%0], [%1], 16;" :: "r"(dst), "l"(src));
}
__device__ __forceinline__ void cp_commit() {
    asm volatile("cp.async.commit_group;");
}
template <int N>
__device__ __forceinline__ void cp_wait() {
    asm volatile("cp.async.wait_group %0;" :: "n"(N));
}
__device__ __forceinline__ void ldsm4(unsigned* r, uint32_t addr) {
    asm volatile("ldmatrix.sync.aligned.m8n8.x4.shared.b16 {%0,%1,%2,%3}, [%4];"
                 : "=r"(r[0]), "=r"(r[1]), "=r"(r[2]), "=r"(r[3]) : "r"(addr));
}

__global__ __launch_bounds__(128, 2) void gemm_kernel(float* __restrict__ out) {
    extern __shared__ char smc[];
    uint32_t sb = smem_u32(smc);

    int tid = threadIdx.x;
    int bm = blockIdx.y * BM, bn = blockIdx.x * BN;
    int warp = tid >> 5, lane = tid & 31;
    int wm = (warp & 1) * 64, wn = (warp >> 1) * 64;
    int grp = lane >> 2, tig = lane & 3;

    // cp.async thread mapping: 16B chunks, swizzle chunk ^= row&7
    int lrow = tid >> 3;            // 0..15
    int lch = tid & 7;              // chunk 0..7
    uint32_t stoffA = lrow * 128 + ((lch ^ (lrow & 7)) << 4);
    uint32_t stoffB = A_BYTES + stoffA;

    const __half* Ag = g_xmh + (size_t)(bm + lrow) * DIM + lch * 8;
    const __half* Bg = g_wh + (size_t)(bn + lrow) * DIM + lch * 8;

    // ldmatrix per-lane address components
    uint32_t aBase[4]; int aR7[4];
    int aCC = lane >> 4;            // kc parity offset
    {
        int r = (lane & 7) + ((lane >> 3) & 1) * 8;
#pragma unroll
        for (int mt = 0; mt < 4; mt++) {
            int row = wm + mt * 16 + r;
            aBase[mt] = row * 128;
            aR7[mt] = row & 7;
        }
    }
    uint32_t bBase[4]; int bR7[4];
    int bCC = (lane >> 3) & 1;
    {
        int r = (lane & 7) + ((lane >> 4) & 1) * 8;
#pragma unroll
        for (int p = 0; p < 4; p++) {
            int row = wn + p * 16 + r;
            bBase[p] = A_BYTES + row * 128;
            bR7[p] = row & 7;
        }
    }

    float acc[4][8][4] = {};

    auto issue = [&](int t) {
        int slot = t % NSTAGE;
        uint32_t base = sb + slot * STAGE_BYTES;
        const __half* Ak = Ag + t * BK;
        const __half* Bk = Bg + t * BK;
#pragma unroll
        for (int o = 0; o < 8; o++)
            cp16(base + stoffA + o * (16 * 128), Ak + (size_t)(o * 16) * DIM);
#pragma unroll
        for (int o = 0; o < 8; o++)
            cp16(base + stoffB + o * (16 * 128), Bk + (size_t)(o * 16) * DIM);
        cp_commit();
    };

    issue(0);
    issue(1);

    int slot = 0;
    for (int j = 0; j < KTILES; j++) {
        // outstanding groups here: {j, j+1} (or {j} on the last iter)
        if (j + 1 < KTILES) { cp_wait<1>(); }
        else { cp_wait<0>(); }
        __syncthreads();   // stage-j visible to all warps; all warps done
                           // reading slot (j-1)%3 == (j+2)%3 -> safe to refill

        uint32_t st = sb + slot * STAGE_BYTES;

        // enqueue next prefetch (into slot (j+2)%3)
        if (j + 2 < KTILES) issue(j + 2);

        unsigned a[2][4][4], b[2][4][4];
        // prime ks=0 fragments
#pragma unroll
        for (int mt = 0; mt < 4; mt++)
            ldsm4(a[0][mt], st + aBase[mt] + ((aCC ^ aR7[mt]) << 4));
#pragma unroll
        for (int p = 0; p < 4; p++)
            ldsm4(b[0][p], st + bBase[p] + ((bCC ^ bR7[p]) << 4));

#pragma unroll
        for (int ks = 0; ks < 4; ks++) {
            int cur = ks & 1, nxt = cur ^ 1;
            if (ks < 3) {
                int kc = 2 * (ks + 1);
#pragma unroll
                for (int mt = 0; mt < 4; mt++)
                    ldsm4(a[nxt][mt], st + aBase[mt] + (((kc + aCC) ^ aR7[mt]) << 4));
#pragma unroll
                for (int p = 0; p < 4; p++)
                    ldsm4(b[nxt][p], st + bBase[p] + (((kc + bCC) ^ bR7[p]) << 4));
            }
#pragma unroll
            for (int mt = 0; mt < 4; mt++)
#pragma unroll
                for (int p = 0; p < 4; p++) {
                    MMA_F16(acc[mt][2 * p], a[cur][mt], b[cur][p][0], b[cur][p][1]);
                    MMA_F16(acc[mt][2 * p + 1], a[cur][mt], b[cur][p][2], b[cur][p][3]);
                }
        }

        slot++; if (slot == NSTAGE) slot = 0;
    }

    // ---- epilogue: float2 stores ----
#pragma unroll
    for (int mt = 0; mt < 4; mt++) {
#pragma unroll
        for (int nt = 0; nt < 8; nt++) {
            int row = bm + wm + mt * 16 + grp;
            int col = bn + wn + nt * 8 + tig * 2;
            float2 v0 = make_float2(acc[mt][nt][0], acc[mt][nt][1]);
            float2 v1 = make_float2(acc[mt][nt][2], acc[mt][nt][3]);
            *(float2*)(out + (size_t)row * DIM + col) = v0;
            *(float2*)(out + (size_t)(row + 8) * DIM + col) = v1;
        }
    }
}

// ---------------------------------------------------------------------------
extern "C" void kernel_launch(void* const* d_in, const int* in_sizes, int n_in,
                              void* d_out, int out_size) {
    const float* x      = (const float*)d_in[0];
    const float* xml    = (const float*)d_in[1];
    const float* fparam = (const float*)d_in[2];
    const float* W      = (const float*)d_in[3];
    float* out = (float*)d_out;

    carryscan_kernel<<<dim3(DIM / 256, NCHUNK), 256>>>(x, fparam);
    carry_kernel<<<DIM / 256, 256>>>(fparam, xml);
    scan_write_kernel<<<dim3(DIM / 256, NCHUNK), 256>>>(x, fparam);
    wconv_kernel<<<(DIM * DIM / 4) / 256, 256>>>(W);

    static bool attr_set = false;
    if (!attr_set) {
        cudaFuncSetAttribute(gemm_kernel, cudaFuncAttributeMaxDynamicSharedMemorySize, SM_BYTES);
        attr_set = true;
    }
    gemm_kernel<<<dim3(DIM / BN, LSEQ / BM), 128, SM_BYTES>>>(out);
}

// round 12
// speedup vs baseline: 1.2367x; 1.0857x over previous
#include <cuda_runtime.h>
#include <cuda_fp16.h>
#include <cstdint>

#define LSEQ 8192
#define DIM  2048
#define NCHUNK 64
#define CHUNK 128

// ---------------- scratch (__device__ globals; no allocation) ---------------
__device__ __half g_xmh[(size_t)LSEQ * DIM];   // x_mix, fp16
__device__ __half g_wh[(size_t)DIM * DIM];     // W, fp16
__device__ float g_carry[NCHUNK * DIM];
__device__ float g_mprev[NCHUNK * DIM];

__device__ __forceinline__ float sigmoidf_(float p) { return 1.0f / (1.0f + expf(-p)); }

// ---------------------------------------------------------------------------
// Pass A: per-chunk carry only (zero-seeded local scan)
// ---------------------------------------------------------------------------
__global__ void carryscan_kernel(const float* __restrict__ x,
                                 const float* __restrict__ fparam) {
    int d = blockIdx.x * blockDim.x + threadIdx.x;
    int c = blockIdx.y;
    float f = sigmoidf_(fparam[d]);
    float omf = 1.0f - f;
    const float* xp = x + (size_t)c * CHUNK * DIM + d;
    float y = 0.0f;
#pragma unroll 16
    for (int i = 0; i < CHUNK; i++)
        y = fmaf(f, y, omf * xp[(size_t)i * DIM]);
    g_carry[c * DIM + d] = y;
}

// ---------------------------------------------------------------------------
// Pass B (fused): serial combine of chunk carries (blockIdx.y == 0, 8 blocks)
// + W -> fp16 conversion (blockIdx.y >= 1, 2048 blocks, 2 float4 each).
// carry work is tiny (2048 threads); W conversion runs on the other SMs
// concurrently instead of as a separate serialized launch.
// ---------------------------------------------------------------------------
#define WBY 256
__global__ void carryw_kernel(const float* __restrict__ fparam,
                              const float* __restrict__ xml,
                              const float* __restrict__ W) {
    if (blockIdx.y == 0) {
        int d = blockIdx.x * blockDim.x + threadIdx.x;
        float f = sigmoidf_(fparam[d]);
        float fC = f;
#pragma unroll
        for (int i = 0; i < 7; i++) fC *= fC;   // f^128
        float m = xml[d];
#pragma unroll 4
        for (int c = 0; c < NCHUNK; c++) {
            g_mprev[c * DIM + d] = m;
            m = fmaf(fC, m, g_carry[c * DIM + d]);
        }
    } else {
        // (WBY * gridDim.x) blocks * 256 threads * 2 float4 = DIM*DIM floats
        int q = ((blockIdx.y - 1) * gridDim.x + blockIdx.x) * blockDim.x + threadIdx.x;
        const int HALF_ELEMS = (DIM * DIM / 4) / 2;   // 524288
        float4 v0 = ((const float4*)W)[q];
        float4 v1 = ((const float4*)W)[q + HALF_ELEMS];
        ((__half2*)g_wh)[q * 2]     = __floats2half2_rn(v0.x, v0.y);
        ((__half2*)g_wh)[q * 2 + 1] = __floats2half2_rn(v0.z, v0.w);
        ((__half2*)g_wh)[(q + HALF_ELEMS) * 2]     = __floats2half2_rn(v1.x, v1.y);
        ((__half2*)g_wh)[(q + HALF_ELEMS) * 2 + 1] = __floats2half2_rn(v1.z, v1.w);
    }
}

// ---------------------------------------------------------------------------
// Pass C: seeded rescan, writes fp16 x_mix.
// ---------------------------------------------------------------------------
__global__ void scan_write_kernel(const float* __restrict__ x,
                                  const float* __restrict__ fparam) {
    int d = blockIdx.x * blockDim.x + threadIdx.x;
    int c = blockIdx.y;
    float f = sigmoidf_(fparam[d]);
    float omf = 1.0f - f;
    const float* xp = x + (size_t)c * CHUNK * DIM + d;
    __half* yp = g_xmh + (size_t)c * CHUNK * DIM + d;
    float y = g_mprev[c * DIM + d];
#pragma unroll 16
    for (int i = 0; i < CHUNK; i++) {
        y = fmaf(f, y, omf * xp[(size_t)i * DIM]);
        yp[(size_t)i * DIM] = __float2half_rn(y);
    }
}

// ---------------------------------------------------------------------------
// fp16 mma.sync GEMM:  out[m,n] = sum_k A[m,k] * W[n,k]  (fp32 accum)
// Block tile 128x128x64, 128 threads = 4 warps (2m x 2n), warp tile 64x64.
// 2 CTAs co-resident per SM, 3-stage cp.async ring (prefetch distance 2),
// ldmatrix.x4 fragments, XOR-swizzled 128B rows, register double-buffering.
// Fragment primes are issued BEFORE the next prefetch burst (primes gate the
// first MMA; the prefetch has a whole ktile of slack).
// ---------------------------------------------------------------------------
#define BM 128
#define BN 128
#define BK 64                                  // halfs; 128 bytes per row
#define KTILES (DIM / BK)                      // 32
#define A_BYTES (BM * 128)                     // 16384
#define B_BYTES (BN * 128)                     // 16384
#define STAGE_BYTES (A_BYTES + B_BYTES)        // 32768
#define NSTAGE 3
#define SM_BYTES (NSTAGE * STAGE_BYTES)        // 98304

#define MMA_F16(c, a, b0, b1)                                                 \
    asm volatile(                                                             \
        "mma.sync.aligned.m16n8k16.row.col.f32.f16.f16.f32 "                  \
        "{%0,%1,%2,%3},{%4,%5,%6,%7},{%8,%9},{%0,%1,%2,%3};\n"                \
        : "+f"((c)[0]), "+f"((c)[1]), "+f"((c)[2]), "+f"((c)[3])              \
        : "r"((a)[0]), "r"((a)[1]), "r"((a)[2]), "r"((a)[3]),                 \
          "r"(b0), "r"(b1))

__device__ __forceinline__ uint32_t smem_u32(const void* p) {
    uint32_t a;
    asm("{ .reg .u64 t; cvta.to.shared.u64 t, %1; cvt.u32.u64 %0, t; }" : "=r"(a) : "l"(p));
    return a;
}
__device__ __forceinline__ void cp16(uint32_t dst, const void* src) {
    asm volatile("cp.async.cg.shared.global [%0], [%1], 16;" :: "r"(dst), "l"(src));
}
__device__ __forceinline__ void cp_commit() {
    asm volatile("cp.async.commit_group;");
}
template <int N>
__device__ __forceinline__ void cp_wait() {
    asm volatile("cp.async.wait_group %0;" :: "n"(N));
}
__device__ __forceinline__ void ldsm4(unsigned* r, uint32_t addr) {
    asm volatile("ldmatrix.sync.aligned.m8n8.x4.shared.b16 {%0,%1,%2,%3}, [%4];"
                 : "=r"(r[0]), "=r"(r[1]), "=r"(r[2]), "=r"(r[3]) : "r"(addr));
}

__global__ __launch_bounds__(128, 2) void gemm_kernel(float* __restrict__ out) {
    extern __shared__ char smc[];
    uint32_t sb = smem_u32(smc);

    int tid = threadIdx.x;
    int bm = blockIdx.y * BM, bn = blockIdx.x * BN;
    int warp = tid >> 5, lane = tid & 31;
    int wm = (warp & 1) * 64, wn = (warp >> 1) * 64;
    int grp = lane >> 2, tig = lane & 3;

    // cp.async thread mapping: 16B chunks, swizzle chunk ^= row&7
    int lrow = tid >> 3;            // 0..15
    int lch = tid & 7;              // chunk 0..7
    uint32_t stoffA = lrow * 128 + ((lch ^ (lrow & 7)) << 4);
    uint32_t stoffB = A_BYTES + stoffA;

    const __half* Ag = g_xmh + (size_t)(bm + lrow) * DIM + lch * 8;
    const __half* Bg = g_wh + (size_t)(bn + lrow) * DIM + lch * 8;

    // ldmatrix per-lane address components
    uint32_t aBase[4]; int aR7[4];
    int aCC = lane >> 4;            // kc parity offset
    {
        int r = (lane & 7) + ((lane >> 3) & 1) * 8;
#pragma unroll
        for (int mt = 0; mt < 4; mt++) {
            int row = wm + mt * 16 + r;
            aBase[mt] = row * 128;
            aR7[mt] = row & 7;
        }
    }
    uint32_t bBase[4]; int bR7[4];
    int bCC = (lane >> 3) & 1;
    {
        int r = (lane & 7) + ((lane >> 4) & 1) * 8;
#pragma unroll
        for (int p = 0; p < 4; p++) {
            int row = wn + p * 16 + r;
            bBase[p] = A_BYTES + row * 128;
            bR7[p] = row & 7;
        }
    }

    float acc[4][8][4] = {};

    auto issue = [&](int t) {
        int slot = t % NSTAGE;
        uint32_t base = sb + slot * STAGE_BYTES;
        const __half* Ak = Ag + t * BK;
        const __half* Bk = Bg + t * BK;
#pragma unroll
        for (int o = 0; o < 8; o++)
            cp16(base + stoffA + o * (16 * 128), Ak + (size_t)(o * 16) * DIM);
#pragma unroll
        for (int o = 0; o < 8; o++)
            cp16(base + stoffB + o * (16 * 128), Bk + (size_t)(o * 16) * DIM);
        cp_commit();
    };

    issue(0);
    issue(1);

    int slot = 0;
    for (int j = 0; j < KTILES; j++) {
        // outstanding groups here: {j, j+1} (or {j} on the last iter)
        if (j + 1 < KTILES) { cp_wait<1>(); }
        else { cp_wait<0>(); }
        __syncthreads();   // stage-j visible to all warps; all warps done
                           // reading slot (j-1)%3 == (j+2)%3 -> safe to refill

        uint32_t st = sb + slot * STAGE_BYTES;

        unsigned a[2][4][4], b[2][4][4];
        // prime ks=0 fragments FIRST (they gate the first MMA of this tile)
#pragma unroll
        for (int mt = 0; mt < 4; mt++)
            ldsm4(a[0][mt], st + aBase[mt] + ((aCC ^ aR7[mt]) << 4));
#pragma unroll
        for (int p = 0; p < 4; p++)
            ldsm4(b[0][p], st + bBase[p] + ((bCC ^ bR7[p]) << 4));

        // then enqueue the next prefetch (into slot (j+2)%3) behind the LDSMs
        if (j + 2 < KTILES) issue(j + 2);

#pragma unroll
        for (int ks = 0; ks < 4; ks++) {
            int cur = ks & 1, nxt = cur ^ 1;
            if (ks < 3) {
                int kc = 2 * (ks + 1);
#pragma unroll
                for (int mt = 0; mt < 4; mt++)
                    ldsm4(a[nxt][mt], st + aBase[mt] + (((kc + aCC) ^ aR7[mt]) << 4));
#pragma unroll
                for (int p = 0; p < 4; p++)
                    ldsm4(b[nxt][p], st + bBase[p] + (((kc + bCC) ^ bR7[p]) << 4));
            }
#pragma unroll
            for (int mt = 0; mt < 4; mt++)
#pragma unroll
                for (int p = 0; p < 4; p++) {
                    MMA_F16(acc[mt][2 * p], a[cur][mt], b[cur][p][0], b[cur][p][1]);
                    MMA_F16(acc[mt][2 * p + 1], a[cur][mt], b[cur][p][2], b[cur][p][3]);
                }
        }

        slot++; if (slot == NSTAGE) slot = 0;
    }

    // ---- epilogue: float2 stores ----
#pragma unroll
    for (int mt = 0; mt < 4; mt++) {
#pragma unroll
        for (int nt = 0; nt < 8; nt++) {
            int row = bm + wm + mt * 16 + grp;
            int col = bn + wn + nt * 8 + tig * 2;
            float2 v0 = make_float2(acc[mt][nt][0], acc[mt][nt][1]);
            float2 v1 = make_float2(acc[mt][nt][2], acc[mt][nt][3]);
            *(float2*)(out + (size_t)row * DIM + col) = v0;
            *(float2*)(out + (size_t)(row + 8) * DIM + col) = v1;
        }
    }
}

// ---------------------------------------------------------------------------
extern "C" void kernel_launch(void* const* d_in, const int* in_sizes, int n_in,
                              void* d_out, int out_size) {
    const float* x      = (const float*)d_in[0];
    const float* xml    = (const float*)d_in[1];
    const float* fparam = (const float*)d_in[2];
    const float* W      = (const float*)d_in[3];
    float* out = (float*)d_out;

    carryscan_kernel<<<dim3(DIM / 256, NCHUNK), 256>>>(x, fparam);
    carryw_kernel<<<dim3(DIM / 256, 1 + WBY), 256>>>(fparam, xml, W);
    scan_write_kernel<<<dim3(DIM / 256, NCHUNK), 256>>>(x, fparam);

    static bool attr_set = false;
    if (!attr_set) {
        cudaFuncSetAttribute(gemm_kernel, cudaFuncAttributeMaxDynamicSharedMemorySize, SM_BYTES);
        attr_set = true;
    }
    gemm_kernel<<<dim3(DIM / BN, LSEQ / BM), 128, SM_BYTES>>>(out);
}